// round 17
// baseline (speedup 1.0000x reference)
#include <cuda_runtime.h>

#define DM 24
#define RD 10
#define NSEQ 512
#define ROWS 4096
#define APAD 12
#define NT 16              // 32-row tiles per batch
#define TS 32
#define NPAIRS 136         // NT*(NT+1)/2
#define NSLOT (NT * 4)     // (other-tile, warp) partial slots
#define CQS 52

typedef unsigned long long u64;

// Scratch (no runtime allocation allowed)
__device__ __align__(16) float g_A[ROWS * APAD];
__device__ __align__(16) float g_Bv[ROWS * APAD];
__device__ __align__(16) float g_psum[NSLOT][ROWS * RD];   // 10.5 MB
__device__ __align__(16) float g_pmax[NSLOT][ROWS * RD];   // 10.5 MB

// ---------------- f32x2 helpers ----------------
__device__ __forceinline__ u64 pk(float lo, float hi) {
    u64 r; asm("mov.b64 %0, {%1, %2};" : "=l"(r) : "f"(lo), "f"(hi)); return r;
}
__device__ __forceinline__ void upk(float& lo, float& hi, u64 v) {
    asm("mov.b64 {%0, %1}, %2;" : "=f"(lo), "=f"(hi) : "l"(v));
}
__device__ __forceinline__ u64 f2fma(u64 a, u64 b, u64 c) {
    u64 d; asm("fma.rn.f32x2 %0, %1, %2, %3;" : "=l"(d) : "l"(a), "l"(b), "l"(c)); return d;
}
__device__ __forceinline__ u64 f2add(u64 a, u64 b) {
    u64 d; asm("add.rn.f32x2 %0, %1, %2;" : "=l"(d) : "l"(a), "l"(b)); return d;
}
__device__ __forceinline__ void lds_v2u64(u64& a, u64& b, const float* p) {
    unsigned sa = (unsigned)__cvta_generic_to_shared((const void*)p);
    asm("ld.shared.v2.u64 {%0, %1}, [%2];" : "=l"(a), "=l"(b) : "r"(sa));
}
__device__ __forceinline__ u64 lds_u64(const float* p) {
    unsigned sa = (unsigned)__cvta_generic_to_shared((const void*)p);
    u64 a; asm("ld.shared.u64 %0, [%1];" : "=l"(a) : "r"(sa));
    return a;
}

// ---------------------------------------------------------------------------
// Kernel 1: precompute, 4 threads per row
// ---------------------------------------------------------------------------
__global__ void precompute_kernel(const float* __restrict__ x,
                                  const float* __restrict__ W1,
                                  const float* __restrict__ b1) {
    int t = blockIdx.x * blockDim.x + threadIdx.x;
    if (t >= ROWS * 4) return;
    int row  = t >> 2;
    int sub  = t & 3;
    int half = sub >> 1;
    int rb   = (sub & 1) * 5;

    float xv[DM];
    {
        const float4* x4 = (const float4*)(x + (size_t)row * DM);
#pragma unroll
        for (int k = 0; k < 6; k++) {
            float4 v = x4[k];
            xv[4*k] = v.x; xv[4*k+1] = v.y; xv[4*k+2] = v.z; xv[4*k+3] = v.w;
        }
    }
    const float* Wb = W1 + half * DM * RD;
    float acc[5];
#pragma unroll
    for (int r = 0; r < 5; r++) acc[r] = half ? 0.f : b1[rb + r];
#pragma unroll
    for (int d = 0; d < DM; d++) {
        float xd = xv[d];
#pragma unroll
        for (int r = 0; r < 5; r++)
            acc[r] = fmaf(xd, Wb[d * RD + rb + r], acc[r]);
    }
    float* dst = half ? g_Bv : g_A;
#pragma unroll
    for (int r = 0; r < 5; r++) dst[row * APAD + rb + r] = acc[r];
    if (rb == 5) { dst[row * APAD + 10] = 0.f; dst[row * APAD + 11] = 0.f; }
}

// ---------------------------------------------------------------------------
// Kernel 2: symmetric tile-pair kernel. Block = 4 warps = one (batch, ti<=tj)
// unit. Lane l owns i = ibase+l; step s pairs it with j = jbase+((l+s)&31).
// The symmetric part S is computed once and finishes BOTH directions; the
// backward result is shuffled to the j-owner lane. Warps split the steps and
// write private partial slots (deterministic, no atomics).
// ---------------------------------------------------------------------------
__global__ __launch_bounds__(128, 4)
void pair_kernel(const float* __restrict__ q,
                 const float* __restrict__ coord,
                 const float* __restrict__ W1,
                 const float* __restrict__ W2,
                 const float* __restrict__ b2) {
    __shared__ __align__(16) float s_icq[TS][CQS];  // -ci | qi (208B rows)
    __shared__ __align__(16) float s_jcq[TS][CQS];  //  cj | qj
    __shared__ __align__(16) float s_ia[TS][14];    // A_i rows (56B stride, u64 access)
    __shared__ __align__(16) float s_ib[TS][14];    // B_i rows
    __shared__ __align__(16) float s_ja[TS][14];    // A_j rows
    __shared__ __align__(16) float s_jb[TS][14];    // B_j rows
    __shared__ __align__(16) float s_w1[26][12];    // [d][r]; 24=qov, 25=dist
    __shared__ __align__(16) float s_w2[10][12];    // [rh][c]

    const int tid = threadIdx.x;
    const int w = tid >> 5, lane = tid & 31;

    // --- unit -> (batch, ti, tj) ---
    int batch = blockIdx.x / NPAIRS;
    int p = blockIdx.x % NPAIRS;
    int ti = 0;
    while (p >= NT - ti) { p -= NT - ti; ti++; }
    const int tj = ti + p;
    const bool diag = (ti == tj);
    const int ibase = batch * NSEQ + ti * TS;
    const int jbase = batch * NSEQ + tj * TS;

    // --- weights ---
    for (int idx = tid; idx < 26 * 12; idx += 128) {
        int d = idx / 12, r = idx % 12;
        float v = 0.f;
        if (r < RD) {
            int row = (d < 24) ? (48 + d) : (d == 24 ? 72 : 73);
            v = W1[row * RD + r];
        }
        s_w1[d][r] = v;
    }
    for (int idx = tid; idx < 10 * 12; idx += 128) {
        int rh = idx / 12, c = idx % 12;
        s_w2[rh][c] = (c < RD) ? W2[rh * RD + c] : 0.f;
    }
    // --- stage i-tile (negated coord) and j-tile ---
    for (int k = tid; k < TS * 6; k += 128) {
        int r = k / 6, cc = k % 6;
        float4 cv = ((const float4*)(coord + (size_t)(ibase + r) * DM))[cc];
        cv.x = -cv.x; cv.y = -cv.y; cv.z = -cv.z; cv.w = -cv.w;
        *(float4*)&s_icq[r][cc * 4] = cv;
        *(float4*)&s_icq[r][24 + cc * 4] = ((const float4*)(q + (size_t)(ibase + r) * DM))[cc];
        *(float4*)&s_jcq[r][cc * 4] = ((const float4*)(coord + (size_t)(jbase + r) * DM))[cc];
        *(float4*)&s_jcq[r][24 + cc * 4] = ((const float4*)(q + (size_t)(jbase + r) * DM))[cc];
    }
    for (int k = tid; k < TS * 6; k += 128) {
        int r = k / 6, cc = (k % 6) * 2;
        *(float2*)&s_ia[r][cc] = *(const float2*)(g_A  + (size_t)(ibase + r) * APAD + cc);
        *(float2*)&s_ib[r][cc] = *(const float2*)(g_Bv + (size_t)(ibase + r) * APAD + cc);
        *(float2*)&s_ja[r][cc] = *(const float2*)(g_A  + (size_t)(jbase + r) * APAD + cc);
        *(float2*)&s_jb[r][cc] = *(const float2*)(g_Bv + (size_t)(jbase + r) * APAD + cc);
    }
    __syncthreads();

    // hoisted per-lane i-row constants
    u64 Ai[5], Bi[5], b2p[5];
#pragma unroll
    for (int t = 0; t < 5; t++) {
        Ai[t] = lds_u64(&s_ia[lane][2 * t]);
        Bi[t] = lds_u64(&s_ib[lane][2 * t]);
        b2p[t] = pk(b2[2 * t], b2[2 * t + 1]);
    }

    float isum[RD], imax[RD], jsum[RD], jmax[RD];
#pragma unroll
    for (int c = 0; c < RD; c++) { isum[c]=0.f; imax[c]=0.f; jsum[c]=0.f; jmax[c]=0.f; }

    // step range for this warp
    int s0, s1;
    if (diag) { s0 = 1 + 4 * w; s1 = s0 + 4; }   // 1..16 total; s=16 fwd-only
    else      { s0 = 8 * w;     s1 = s0 + 8; }   // 0..31

    for (int s = s0; s < s1; ++s) {
        const int jl = (lane + s) & 31;
        const bool do_bwd = !(diag && s == 16);

        // symmetric part S
        u64 S[5];
#pragma unroll
        for (int t = 0; t < 5; t++) S[t] = 0ull;
        u64 d2p = 0ull, qdp = 0ull;
#pragma unroll
        for (int kk = 0; kk < 6; kk++) {
            float4 nci4 = *(const float4*)&s_icq[lane][4 * kk];
            float4 qi4  = *(const float4*)&s_icq[lane][24 + 4 * kk];
            float4 cj4  = *(const float4*)&s_jcq[jl][4 * kk];
            float4 qj4  = *(const float4*)&s_jcq[jl][24 + 4 * kk];
#pragma unroll
            for (int ep = 0; ep < 2; ep++) {
                const int d = 4 * kk + 2 * ep;
                u64 ncip = ep ? pk(nci4.z, nci4.w) : pk(nci4.x, nci4.y);
                u64 qip  = ep ? pk(qi4.z,  qi4.w)  : pk(qi4.x,  qi4.y);
                u64 cjp  = ep ? pk(cj4.z,  cj4.w)  : pk(cj4.x,  cj4.y);
                u64 qjp  = ep ? pk(qj4.z,  qj4.w)  : pk(qj4.x,  qj4.y);
                u64 mdfp = f2add(ncip, cjp);          // {-df_d, -df_d+1}
                d2p = f2fma(mdfp, mdfp, d2p);
                qdp = f2fma(qip, qjp, qdp);
                float m0, m1;
                upk(m0, m1, mdfp);
                float a0 = fabsf(m0), a1 = fabsf(m1);
                u64 av0 = pk(a0, a0), av1 = pk(a1, a1);
                u64 wA[5], wB[5];
                lds_v2u64(wA[0], wA[1], &s_w1[d][0]);
                lds_v2u64(wA[2], wA[3], &s_w1[d][4]);
                wA[4] = lds_u64(&s_w1[d][8]);
                lds_v2u64(wB[0], wB[1], &s_w1[d + 1][0]);
                lds_v2u64(wB[2], wB[3], &s_w1[d + 1][4]);
                wB[4] = lds_u64(&s_w1[d + 1][8]);
#pragma unroll
                for (int t = 0; t < 5; t++) {
                    S[t] = f2fma(av0, wA[t], S[t]);
                    S[t] = f2fma(av1, wB[t], S[t]);
                }
            }
        }
        // tail features
        {
            float de, do_, qe, qo;
            upk(de, do_, d2p);
            upk(qe, qo, qdp);
            float dist = sqrtf(de + do_);
            float qd = qe + qo;
            u64 qp = pk(qd, qd), dp = pk(dist, dist);
            u64 wq[5], wd[5];
            lds_v2u64(wq[0], wq[1], &s_w1[24][0]);
            lds_v2u64(wq[2], wq[3], &s_w1[24][4]);
            wq[4] = lds_u64(&s_w1[24][8]);
            lds_v2u64(wd[0], wd[1], &s_w1[25][0]);
            lds_v2u64(wd[2], wd[3], &s_w1[25][4]);
            wd[4] = lds_u64(&s_w1[25][8]);
#pragma unroll
            for (int t = 0; t < 5; t++) {
                S[t] = f2fma(qp, wq[t], S[t]);
                S[t] = f2fma(dp, wd[t], S[t]);
            }
        }
        // hidden layer, both directions
        float haf[RD], hab[RD];
        {
#pragma unroll
            for (int t = 0; t < 5; t++) {
                u64 Aj = lds_u64(&s_ja[jl][2 * t]);
                u64 Bj = lds_u64(&s_jb[jl][2 * t]);
                float lo, hi;
                u64 hf = f2add(f2add(S[t], Ai[t]), Bj);
                upk(lo, hi, hf);
                haf[2*t]   = fmaxf(lo, 0.f);
                haf[2*t+1] = fmaxf(hi, 0.f);
                u64 hb = f2add(f2add(S[t], Aj), Bi[t]);
                upk(lo, hi, hb);
                hab[2*t]   = fmaxf(lo, 0.f);
                hab[2*t+1] = fmaxf(hi, 0.f);
            }
        }
        // layer 2, shared weight loads
        u64 r2f[5], r2b[5];
#pragma unroll
        for (int t = 0; t < 5; t++) { r2f[t] = b2p[t]; r2b[t] = b2p[t]; }
#pragma unroll
        for (int rh = 0; rh < RD; rh++) {
            u64 wv[5];
            lds_v2u64(wv[0], wv[1], &s_w2[rh][0]);
            lds_v2u64(wv[2], wv[3], &s_w2[rh][4]);
            wv[4] = lds_u64(&s_w2[rh][8]);
            u64 hhf = pk(haf[rh], haf[rh]);
            u64 hhb = pk(hab[rh], hab[rh]);
#pragma unroll
            for (int t = 0; t < 5; t++) {
                r2f[t] = f2fma(hhf, wv[t], r2f[t]);
                r2b[t] = f2fma(hhb, wv[t], r2b[t]);
            }
        }
        // forward accumulate (row ibase+lane)
#pragma unroll
        for (int t = 0; t < 5; t++) {
            float v0, v1;
            upk(v0, v1, r2f[t]);
            v0 = fmaxf(v0, 0.f); v1 = fmaxf(v1, 0.f);
            isum[2*t]   += v0;  imax[2*t]   = fmaxf(imax[2*t],   v0);
            isum[2*t+1] += v1;  imax[2*t+1] = fmaxf(imax[2*t+1], v1);
        }
        // backward: shuffle to the j-owner lane (row jbase+lane)
        if (do_bwd) {
            const int src = (lane - s) & 31;
#pragma unroll
            for (int t = 0; t < 5; t++) {
                float v0, v1;
                upk(v0, v1, r2b[t]);
                v0 = __shfl_sync(0xffffffffu, v0, src);
                v1 = __shfl_sync(0xffffffffu, v1, src);
                v0 = fmaxf(v0, 0.f); v1 = fmaxf(v1, 0.f);
                jsum[2*t]   += v0;  jmax[2*t]   = fmaxf(jmax[2*t],   v0);
                jsum[2*t+1] += v1;  jmax[2*t+1] = fmaxf(jmax[2*t+1], v1);
            }
        }
    }

    // write per-warp partial slots
    if (diag) {
#pragma unroll
        for (int c = 0; c < RD; c++) {
            isum[c] += jsum[c];
            imax[c] = fmaxf(imax[c], jmax[c]);
        }
    }
    {
        float* ps = &g_psum[tj * 4 + w][(size_t)(ibase + lane) * RD];
        float* pm = &g_pmax[tj * 4 + w][(size_t)(ibase + lane) * RD];
#pragma unroll
        for (int c = 0; c < RD; c++) { ps[c] = isum[c]; pm[c] = imax[c]; }
    }
    if (!diag) {
        float* ps = &g_psum[ti * 4 + w][(size_t)(jbase + lane) * RD];
        float* pm = &g_pmax[ti * 4 + w][(size_t)(jbase + lane) * RD];
#pragma unroll
        for (int c = 0; c < RD; c++) { ps[c] = jsum[c]; pm[c] = jmax[c]; }
    }
}

// ---------------------------------------------------------------------------
// Kernel 3: reduce 64 slots -> final mean / max
// ---------------------------------------------------------------------------
__global__ void reduce_kernel(float* __restrict__ out) {
    int gid = blockIdx.x * blockDim.x + threadIdx.x;
    if (gid >= ROWS * RD) return;
    float s = 0.f, m = 0.f;
#pragma unroll
    for (int k = 0; k < NSLOT; k++) {
        s += g_psum[k][gid];
        m = fmaxf(m, g_pmax[k][gid]);
    }
    out[gid] = s * (1.0f / (float)(NSEQ - 1));
    out[ROWS * RD + gid] = m;
}

// ---------------------------------------------------------------------------
extern "C" void kernel_launch(void* const* d_in, const int* in_sizes, int n_in,
                              void* d_out, int out_size) {
    const float* x     = (const float*)d_in[0];
    const float* q     = (const float*)d_in[1];
    const float* coord = (const float*)d_in[2];
    const float* W1    = (const float*)d_in[3];
    const float* b1    = (const float*)d_in[4];
    const float* W2    = (const float*)d_in[5];
    const float* b2    = (const float*)d_in[6];
    float* out = (float*)d_out;

    precompute_kernel<<<(ROWS * 4 + 127) / 128, 128>>>(x, W1, b1);
    pair_kernel<<<8 * NPAIRS, 128>>>(q, coord, W1, W2, b2);
    reduce_kernel<<<(ROWS * RD + 255) / 256, 256>>>(out);
}